// round 4
// baseline (speedup 1.0000x reference)
#include <cuda_runtime.h>

// Problem constants (fixed shapes from reference setup_inputs)
#define NB   2
#define C    32
#define H    64
#define W    64
#define L    (H * W)      // 4096
#define CKK  288          // C * 3 * 3
#define O    32           // out channels == warp lanes
#define WARPS_PER_BLOCK 8
#define THREADS (WARPS_PER_BLOCK * 32)

// One warp per (n, l) spatial location.
// Phase 1: warp builds the 288-float unfold patch in shared memory
//          (features are only 2MB -> L2 resident, 9x reuse).
// Phase 2: lane = output channel. Each lane streams filters[n,l,k,lane]
//          (stride 32 floats along k -> the warp reads one full 128B line
//          per k, perfectly coalesced), FFMA vs LDS-broadcast patch value.
__global__ __launch_bounds__(THREADS)
void convfilt_kernel(const float* __restrict__ features,
                     const float* __restrict__ filters,
                     float* __restrict__ out)
{
    __shared__ float s_patch[WARPS_PER_BLOCK][CKK];

    const int warp = threadIdx.x >> 5;
    const int lane = threadIdx.x & 31;
    const int gw   = blockIdx.x * WARPS_PER_BLOCK + warp;  // 0 .. N*L-1
    const int n    = gw >> 12;        // / 4096
    const int l    = gw & (L - 1);
    const int h    = l >> 6;
    const int w    = l & (W - 1);

    // ---- Phase 1: build unfold patch (k = c*9 + kh*3 + kw) ----
    #pragma unroll
    for (int k = lane; k < CKK; k += 32) {
        const int c  = k / 9;
        const int r  = k - c * 9;
        const int kh = r / 3;
        const int kw = r - kh * 3;
        const int hh = h + kh - 1;
        const int ww = w + kw - 1;
        float v = 0.0f;
        if ((unsigned)hh < (unsigned)H && (unsigned)ww < (unsigned)W)
            v = features[((n * C + c) * H + hh) * W + ww];
        s_patch[warp][k] = v;
    }
    __syncwarp();

    // ---- Phase 2: stream filters (302MB total, read exactly once) ----
    const float* __restrict__ fp =
        filters + (long long)(n * L + l) * (CKK * O) + lane;

    float acc = 0.0f;
    #pragma unroll 8
    for (int k = 0; k < CKK; ++k) {
        acc = fmaf(s_patch[warp][k], fp[(long long)k * O], acc);
    }

    // out[n, o=lane, l] with ReLU
    out[(n * O + lane) * L + l] = fmaxf(acc, 0.0f);
}

extern "C" void kernel_launch(void* const* d_in, const int* in_sizes, int n_in,
                              void* d_out, int out_size)
{
    const float* features = (const float*)d_in[0];  // [2,32,64,64]
    const float* filters  = (const float*)d_in[1];  // [2,4096,288,32]
    float* out = (float*)d_out;                     // [2,32,64,64]

    const int total_warps = NB * L;                 // 8192
    const int grid = total_warps / WARPS_PER_BLOCK; // 1024
    convfilt_kernel<<<grid, THREADS>>>(features, filters, out);
}

// round 5
// speedup vs baseline: 1.0685x; 1.0685x over previous
#include <cuda_runtime.h>

// Problem constants (fixed shapes from reference setup_inputs)
#define NB   2
#define C    32
#define H    64
#define W    64
#define L    (H * W)      // 4096
#define CKK  288          // C * 3 * 3
#define O    32           // out channels
#define WARPS_PER_BLOCK 8
#define THREADS (WARPS_PER_BLOCK * 32)

// One warp per (n, l) spatial location.
// Phase 1: warp builds the 288-float unfold patch in shared memory
//          (features are 2MB -> L2 resident, 9x reuse).
// Phase 2: lane split: og = lane&7 selects a quad of output channels
//          (float4 over o), kg = lane>>3 selects a k-slice (k = kg+4t).
//          Each lane: 72 x LDG.128 of filters, 4 independent FMA chains.
//          Reduce the 4 k-slices with shfl_xor(8), shfl_xor(16).
__global__ __launch_bounds__(THREADS)
void convfilt_kernel(const float* __restrict__ features,
                     const float* __restrict__ filters,
                     float* __restrict__ out)
{
    __shared__ float s_patch[WARPS_PER_BLOCK][CKK];

    const int warp = threadIdx.x >> 5;
    const int lane = threadIdx.x & 31;
    const int gw   = blockIdx.x * WARPS_PER_BLOCK + warp;  // 0 .. N*L-1
    const int n    = gw >> 12;        // / 4096
    const int l    = gw & (L - 1);
    const int h    = l >> 6;
    const int w    = l & (W - 1);

    // ---- Phase 1: build unfold patch (k = c*9 + kh*3 + kw) ----
    #pragma unroll
    for (int k = lane; k < CKK; k += 32) {
        const int c  = k / 9;
        const int r  = k - c * 9;
        const int kh = r / 3;
        const int kw = r - kh * 3;
        const int hh = h + kh - 1;
        const int ww = w + kw - 1;
        float v = 0.0f;
        if ((unsigned)hh < (unsigned)H && (unsigned)ww < (unsigned)W)
            v = features[((n * C + c) * H + hh) * W + ww];
        s_patch[warp][k] = v;
    }
    __syncwarp();

    // ---- Phase 2: stream filters with LDG.128 ----
    const int og = lane & 7;    // output quad: channels og*4 .. og*4+3
    const int kg = lane >> 3;   // k-slice: k = kg, kg+4, kg+8, ...

    const float4* __restrict__ fp = (const float4*)
        (filters + (long long)(n * L + l) * (CKK * O) + og * 4);
    // element k, quad og lives at fp[k * (O/4)] = fp[k * 8]

    float4 acc = make_float4(0.f, 0.f, 0.f, 0.f);
    #pragma unroll 8
    for (int t = 0; t < CKK / 4; ++t) {          // 72 iterations
        const int k = kg + 4 * t;
        const float s  = s_patch[warp][k];
        const float4 f = fp[(long long)k * 8];
        acc.x = fmaf(s, f.x, acc.x);
        acc.y = fmaf(s, f.y, acc.y);
        acc.z = fmaf(s, f.z, acc.z);
        acc.w = fmaf(s, f.w, acc.w);
    }

    // ---- Reduce across the 4 k-slices (lanes differing in bits 3,4) ----
    #pragma unroll
    for (int m = 8; m <= 16; m <<= 1) {
        acc.x += __shfl_xor_sync(0xffffffffu, acc.x, m);
        acc.y += __shfl_xor_sync(0xffffffffu, acc.y, m);
        acc.z += __shfl_xor_sync(0xffffffffu, acc.z, m);
        acc.w += __shfl_xor_sync(0xffffffffu, acc.w, m);
    }

    // lanes 0..7 (kg==0) hold the full sums for channels og*4 .. og*4+3
    if (kg == 0) {
        const int obase = og * 4;
        out[(n * O + obase + 0) * L + l] = fmaxf(acc.x, 0.0f);
        out[(n * O + obase + 1) * L + l] = fmaxf(acc.y, 0.0f);
        out[(n * O + obase + 2) * L + l] = fmaxf(acc.z, 0.0f);
        out[(n * O + obase + 3) * L + l] = fmaxf(acc.w, 0.0f);
    }
}

extern "C" void kernel_launch(void* const* d_in, const int* in_sizes, int n_in,
                              void* d_out, int out_size)
{
    const float* features = (const float*)d_in[0];  // [2,32,64,64]
    const float* filters  = (const float*)d_in[1];  // [2,4096,288,32]
    float* out = (float*)d_out;                     // [2,32,64,64]

    const int total_warps = NB * L;                 // 8192
    const int grid = total_warps / WARPS_PER_BLOCK; // 1024
    convfilt_kernel<<<grid, THREADS>>>(features, filters, out);
}

// round 7
// speedup vs baseline: 1.1047x; 1.0339x over previous
#include <cuda_runtime.h>

// Problem constants (fixed shapes from reference setup_inputs)
#define NB   2
#define C    32
#define H    64
#define W    64
#define L    (H * W)      // 4096
#define CKK  288          // C * 3 * 3
#define O    32           // out channels
#define WARPS_PER_BLOCK 8
#define THREADS (WARPS_PER_BLOCK * 32)

__device__ __forceinline__ float4 ldcs4(const float4* p) {
    return __ldcs(p);   // LDG.128 evict-first: filters are read exactly once
}

// One warp per (n, l) spatial location.
// Phase 0: peel first 2 filter float4 loads (independent of patch) so DRAM
//          traffic is in flight while phase 1 waits on L2.
// Phase 1: warp builds the 288-float unfold patch in shared memory
//          (features are 2MB -> kept L2 resident because filters use .cs).
// Phase 2: lane split: og = lane&7 -> quad of output channels (float4 over o),
//          kg = lane>>3 -> k-slice (k = kg+4t). 72 x LDG.128.STRM per lane,
//          4 independent FMA chains, shfl_xor(8,16) reduction.
__global__ __launch_bounds__(THREADS)
void convfilt_kernel(const float* __restrict__ features,
                     const float* __restrict__ filters,
                     float* __restrict__ out)
{
    __shared__ float s_patch[WARPS_PER_BLOCK][CKK];

    const int warp = threadIdx.x >> 5;
    const int lane = threadIdx.x & 31;
    const int gw   = blockIdx.x * WARPS_PER_BLOCK + warp;  // 0 .. N*L-1
    const int n    = gw >> 12;        // / 4096
    const int l    = gw & (L - 1);
    const int h    = l >> 6;
    const int w    = l & (W - 1);

    const int og = lane & 7;    // output quad: channels og*4 .. og*4+3
    const int kg = lane >> 3;   // k-slice: k = kg, kg+4, kg+8, ...

    const float4* __restrict__ fp = (const float4*)
        (filters + (long long)(n * L + l) * (CKK * O) + og * 4);
    // element k, quad og lives at fp[k * (O/4)] = fp[k * 8]

    // ---- Phase 0: peel first two filter loads (independent of patch) ----
    const float4 f0 = ldcs4(fp + (long long)(kg      ) * 8);   // t = 0
    const float4 f1 = ldcs4(fp + (long long)(kg + 4  ) * 8);   // t = 1

    // ---- Phase 1: build unfold patch (k = c*9 + kh*3 + kw) ----
    #pragma unroll
    for (int k = lane; k < CKK; k += 32) {
        const int c  = k / 9;
        const int r  = k - c * 9;
        const int kh = r / 3;
        const int kw = r - kh * 3;
        const int hh = h + kh - 1;
        const int ww = w + kw - 1;
        float v = 0.0f;
        if ((unsigned)hh < (unsigned)H && (unsigned)ww < (unsigned)W)
            v = features[((n * C + c) * H + hh) * W + ww];
        s_patch[warp][k] = v;
    }
    __syncwarp();

    // ---- Phase 2: consume peeled loads, then stream the rest ----
    float4 acc = make_float4(0.f, 0.f, 0.f, 0.f);
    {
        const float s0 = s_patch[warp][kg];
        acc.x = fmaf(s0, f0.x, acc.x);
        acc.y = fmaf(s0, f0.y, acc.y);
        acc.z = fmaf(s0, f0.z, acc.z);
        acc.w = fmaf(s0, f0.w, acc.w);
        const float s1 = s_patch[warp][kg + 4];
        acc.x = fmaf(s1, f1.x, acc.x);
        acc.y = fmaf(s1, f1.y, acc.y);
        acc.z = fmaf(s1, f1.z, acc.z);
        acc.w = fmaf(s1, f1.w, acc.w);
    }

    #pragma unroll 7
    for (int t = 2; t < CKK / 4; ++t) {          // 70 iterations
        const int k = kg + 4 * t;
        const float s  = s_patch[warp][k];
        const float4 f = ldcs4(fp + (long long)k * 8);
        acc.x = fmaf(s, f.x, acc.x);
        acc.y = fmaf(s, f.y, acc.y);
        acc.z = fmaf(s, f.z, acc.z);
        acc.w = fmaf(s, f.w, acc.w);
    }

    // ---- Reduce across the 4 k-slices (lanes differing in bits 3,4) ----
    #pragma unroll
    for (int m = 8; m <= 16; m <<= 1) {
        acc.x += __shfl_xor_sync(0xffffffffu, acc.x, m);
        acc.y += __shfl_xor_sync(0xffffffffu, acc.y, m);
        acc.z += __shfl_xor_sync(0xffffffffu, acc.z, m);
        acc.w += __shfl_xor_sync(0xffffffffu, acc.w, m);
    }

    // lanes 0..7 (kg==0) hold the full sums for channels og*4 .. og*4+3
    if (kg == 0) {
        const int obase = og * 4;
        __stcs(&out[(n * O + obase + 0) * L + l], fmaxf(acc.x, 0.0f));
        __stcs(&out[(n * O + obase + 1) * L + l], fmaxf(acc.y, 0.0f));
        __stcs(&out[(n * O + obase + 2) * L + l], fmaxf(acc.z, 0.0f));
        __stcs(&out[(n * O + obase + 3) * L + l], fmaxf(acc.w, 0.0f));
    }
}

extern "C" void kernel_launch(void* const* d_in, const int* in_sizes, int n_in,
                              void* d_out, int out_size)
{
    const float* features = (const float*)d_in[0];  // [2,32,64,64]
    const float* filters  = (const float*)d_in[1];  // [2,4096,288,32]
    float* out = (float*)d_out;                     // [2,32,64,64]

    const int total_warps = NB * L;                 // 8192
    const int grid = total_warps / WARPS_PER_BLOCK; // 1024
    convfilt_kernel<<<grid, THREADS>>>(features, filters, out);
}

// round 8
// speedup vs baseline: 1.1108x; 1.0056x over previous
#include <cuda_runtime.h>

// Problem constants (fixed shapes from reference setup_inputs)
#define NB   2
#define C    32
#define H    64
#define W    64
#define L    (H * W)      // 4096
#define CKK  288          // C * 3 * 3
#define O    32           // out channels
#define WARPS_PER_BLOCK 8
#define THREADS (WARPS_PER_BLOCK * 32)

__device__ __forceinline__ float4 ldcs4(const float4* p) {
    return __ldcs(p);   // LDG.128 evict-first: filters are read exactly once
}

// One warp per (n, l) spatial location.
// Phase 0: peel first 2 filter float4 loads (independent of patch).
// Phase 1: warp builds the 288-float unfold patch in shared memory.
// Phase 2: FULLY UNROLLED filter stream (72 independent LDG.128 per lane);
//          __launch_bounds__(256, 6) gives ptxas ~42 regs so it can keep
//          ~6-8 loads in flight per lane (vs ~3 at the old 32-reg budget).
__global__ __launch_bounds__(THREADS, 6)
void convfilt_kernel(const float* __restrict__ features,
                     const float* __restrict__ filters,
                     float* __restrict__ out)
{
    __shared__ float s_patch[WARPS_PER_BLOCK][CKK];

    const int warp = threadIdx.x >> 5;
    const int lane = threadIdx.x & 31;
    const int gw   = blockIdx.x * WARPS_PER_BLOCK + warp;  // 0 .. N*L-1
    const int n    = gw >> 12;        // / 4096
    const int l    = gw & (L - 1);
    const int h    = l >> 6;
    const int w    = l & (W - 1);

    const int og = lane & 7;    // output quad: channels og*4 .. og*4+3
    const int kg = lane >> 3;   // k-slice: k = kg, kg+4, kg+8, ...

    const float4* __restrict__ fp = (const float4*)
        (filters + (long long)(n * L + l) * (CKK * O) + og * 4);
    // element k, quad og lives at fp[k * (O/4)] = fp[k * 8]

    // ---- Phase 0: peel first two filter loads (independent of patch) ----
    const float4 f0 = ldcs4(fp + (long long)(kg    ) * 8);   // t = 0
    const float4 f1 = ldcs4(fp + (long long)(kg + 4) * 8);   // t = 1

    // ---- Phase 1: build unfold patch (k = c*9 + kh*3 + kw) ----
    #pragma unroll
    for (int k = lane; k < CKK; k += 32) {
        const int c  = k / 9;
        const int r  = k - c * 9;
        const int kh = r / 3;
        const int kw = r - kh * 3;
        const int hh = h + kh - 1;
        const int ww = w + kw - 1;
        float v = 0.0f;
        if ((unsigned)hh < (unsigned)H && (unsigned)ww < (unsigned)W)
            v = features[((n * C + c) * H + hh) * W + ww];
        s_patch[warp][k] = v;
    }
    __syncwarp();

    // ---- Phase 2: consume peeled loads, then stream the rest ----
    float4 acc = make_float4(0.f, 0.f, 0.f, 0.f);
    {
        const float s0 = s_patch[warp][kg];
        acc.x = fmaf(s0, f0.x, acc.x);
        acc.y = fmaf(s0, f0.y, acc.y);
        acc.z = fmaf(s0, f0.z, acc.z);
        acc.w = fmaf(s0, f0.w, acc.w);
        const float s1 = s_patch[warp][kg + 4];
        acc.x = fmaf(s1, f1.x, acc.x);
        acc.y = fmaf(s1, f1.y, acc.y);
        acc.z = fmaf(s1, f1.z, acc.z);
        acc.w = fmaf(s1, f1.w, acc.w);
    }

    // Fully unrolled: 70 independent LDG.128, globally schedulable by ptxas.
    #pragma unroll
    for (int t = 2; t < CKK / 4; ++t) {
        const int k = kg + 4 * t;
        const float s  = s_patch[warp][k];
        const float4 f = ldcs4(fp + (long long)k * 8);
        acc.x = fmaf(s, f.x, acc.x);
        acc.y = fmaf(s, f.y, acc.y);
        acc.z = fmaf(s, f.z, acc.z);
        acc.w = fmaf(s, f.w, acc.w);
    }

    // ---- Reduce across the 4 k-slices (lanes differing in bits 3,4) ----
    #pragma unroll
    for (int m = 8; m <= 16; m <<= 1) {
        acc.x += __shfl_xor_sync(0xffffffffu, acc.x, m);
        acc.y += __shfl_xor_sync(0xffffffffu, acc.y, m);
        acc.z += __shfl_xor_sync(0xffffffffu, acc.z, m);
        acc.w += __shfl_xor_sync(0xffffffffu, acc.w, m);
    }

    // lanes 0..7 (kg==0) hold the full sums for channels og*4 .. og*4+3
    if (kg == 0) {
        const int obase = og * 4;
        __stcs(&out[(n * O + obase + 0) * L + l], fmaxf(acc.x, 0.0f));
        __stcs(&out[(n * O + obase + 1) * L + l], fmaxf(acc.y, 0.0f));
        __stcs(&out[(n * O + obase + 2) * L + l], fmaxf(acc.z, 0.0f));
        __stcs(&out[(n * O + obase + 3) * L + l], fmaxf(acc.w, 0.0f));
    }
}

extern "C" void kernel_launch(void* const* d_in, const int* in_sizes, int n_in,
                              void* d_out, int out_size)
{
    const float* features = (const float*)d_in[0];  // [2,32,64,64]
    const float* filters  = (const float*)d_in[1];  // [2,4096,288,32]
    float* out = (float*)d_out;                     // [2,32,64,64]

    const int total_warps = NB * L;                 // 8192
    const int grid = total_warps / WARPS_PER_BLOCK; // 1024
    convfilt_kernel<<<grid, THREADS>>>(features, filters, out);
}